// round 1
// baseline (speedup 1.0000x reference)
#include <cuda_runtime.h>
#include <cuda_bf16.h>

// PointPWC multi-scale loss (single scale), B=1, N=8192.
// total = 0.02*chamfer + 0.006*curv + 0.01*smooth
//
// Structure:
//   prep:            pc1/pc2/warp/flow as float4 (w = |p|^2), zero accumulators
//   knn_partial<Q,P>: candidate axis split into CHUNKS; per-chunk sorted top-10
//                     written to scratch (stable, ascending j)
//   merge+consume:   linear stable scan of CHUNKS*KNN sorted partials -> top-10
//   min_partial/rev: reverse chamfer min
//   finalize:        combine double accumulators -> out[0]

#define MAXN   8192
#define CHUNKS 8
#define KNN    10
#define TPB    128

__device__ float4 g_pc1[MAXN];
__device__ float4 g_pc2[MAXN];
__device__ float4 g_warp[MAXN];
__device__ float4 g_flow[MAXN];
__device__ float4 g_c2[MAXN];
__device__ float4 g_moved[MAXN];
__device__ float  g_pd[MAXN * CHUNKS * KNN];
__device__ int    g_pi[MAXN * CHUNKS * KNN];
__device__ float  g_pmin[MAXN * CHUNKS];
__device__ double g_acc[4];  // 0: chamfer fwd, 1: chamfer bwd, 2: smooth, 3: curv

__device__ __forceinline__ double warp_red(double v) {
    #pragma unroll
    for (int o = 16; o > 0; o >>= 1)
        v += __shfl_down_sync(0xffffffffu, v, o);
    return v;
}

__global__ void prep_kernel(const float* __restrict__ pred,
                            const float* __restrict__ gt,
                            const float* __restrict__ coords, int n) {
    int i = blockIdx.x * blockDim.x + threadIdx.x;
    if (i == 0) { g_acc[0] = 0.0; g_acc[1] = 0.0; g_acc[2] = 0.0; g_acc[3] = 0.0; }
    if (i >= n) return;
    float cx = coords[3 * i + 0], cy = coords[3 * i + 1], cz = coords[3 * i + 2];
    float gx = gt[3 * i + 0],     gy = gt[3 * i + 1],     gz = gt[3 * i + 2];
    float fx = pred[3 * i + 0],   fy = pred[3 * i + 1],   fz = pred[3 * i + 2];
    float p2x = cx + gx, p2y = cy + gy, p2z = cz + gz;
    float wx  = cx + fx, wy  = cy + fy, wz  = cz + fz;
    g_pc1[i]  = make_float4(cx, cy, cz, cx * cx + cy * cy + cz * cz);
    g_pc2[i]  = make_float4(p2x, p2y, p2z, p2x * p2x + p2y * p2y + p2z * p2z);
    g_warp[i] = make_float4(wx, wy, wz, wx * wx + wy * wy + wz * wz);
    g_flow[i] = make_float4(fx, fy, fz, 0.f);
}

// QS/PS: 0=pc1, 1=pc2, 2=warp. Partial top-KNN over candidate chunk blockIdx.y.
template <int QS, int PS>
__global__ void knn_partial_kernel(int n) {
    const float4* __restrict__ Q = (QS == 0) ? g_pc1 : ((QS == 1) ? g_pc2 : g_warp);
    const float4* __restrict__ P = (PS == 0) ? g_pc1 : ((PS == 1) ? g_pc2 : g_warp);
    __shared__ float4 sp[TPB];
    int i = blockIdx.x * TPB + threadIdx.x;
    int chunk = n / CHUNKS;
    int j0 = blockIdx.y * chunk;
    int j1 = j0 + chunk;
    float4 q = Q[i < n ? i : 0];
    float qn = q.w;
    float d[KNN]; int id[KNN];
    #pragma unroll
    for (int t = 0; t < KNN; t++) { d[t] = 3.4e38f; id[t] = 0; }
    for (int jb = j0; jb < j1; jb += TPB) {
        __syncthreads();
        sp[threadIdx.x] = P[jb + threadIdx.x];
        __syncthreads();
        #pragma unroll 4
        for (int t = 0; t < TPB; t++) {
            float4 p = sp[t];
            float dot  = fmaf(q.x, p.x, fmaf(q.y, p.y, q.z * p.z));
            float dist = fmaf(-2.f, dot, qn + p.w);
            if (dist < d[KNN - 1]) {
                d[KNN - 1] = dist; id[KNN - 1] = jb + t;
                #pragma unroll
                for (int s = KNN - 1; s > 0; --s) {
                    if (d[s] < d[s - 1]) {
                        float td = d[s]; d[s] = d[s - 1]; d[s - 1] = td;
                        int   ti = id[s]; id[s] = id[s - 1]; id[s - 1] = ti;
                    }
                }
            }
        }
    }
    if (i < n) {
        int base = (i * CHUNKS + blockIdx.y) * KNN;
        #pragma unroll
        for (int t = 0; t < KNN; t++) { g_pd[base + t] = d[t]; g_pi[base + t] = id[t]; }
    }
}

// Stable merge: partials are stored chunk-major with ascending j within chunk,
// and chunk c covers ascending j ranges, so a linear strict-insert scan keeps
// the same tie-order as lax.top_k (earliest index wins on ties).
__device__ __forceinline__ void merge_topk(int i, float* d, int* id) {
    #pragma unroll
    for (int t = 0; t < KNN; t++) { d[t] = 3.4e38f; id[t] = 0; }
    int base = i * CHUNKS * KNN;
    for (int t = 0; t < CHUNKS * KNN; t++) {
        float dist = g_pd[base + t];
        int j = g_pi[base + t];
        if (dist < d[KNN - 1]) {
            d[KNN - 1] = dist; id[KNN - 1] = j;
            #pragma unroll
            for (int s = KNN - 1; s > 0; --s) {
                if (d[s] < d[s - 1]) {
                    float td = d[s]; d[s] = d[s - 1]; d[s - 1] = td;
                    int   ti = id[s]; id[s] = id[s - 1]; id[s - 1] = ti;
                }
            }
        }
    }
}

// pc2 self-knn -> curvature of pc2
__global__ void curv2_kernel(int n) {
    int i = blockIdx.x * blockDim.x + threadIdx.x;
    if (i >= n) return;
    float d[KNN]; int id[KNN];
    merge_topk(i, d, id);
    float sx = 0.f, sy = 0.f, sz = 0.f;
    #pragma unroll
    for (int t = 0; t < KNN; t++) {
        float4 p = g_pc2[id[t]];
        sx += p.x; sy += p.y; sz += p.z;
    }
    float4 c = g_pc2[i];
    g_c2[i] = make_float4((sx - 10.f * c.x) / 9.f,
                          (sy - 10.f * c.y) / 9.f,
                          (sz - 10.f * c.z) / 9.f, 0.f);
}

// pc1 self-knn -> moved curvature (k=10) + smoothness (k = *kptr <= 10)
__global__ void pc1_consume_kernel(int n, const int* __restrict__ kptr) {
    int i = blockIdx.x * blockDim.x + threadIdx.x;
    double sm_d = 0.0;
    if (i < n) {
        float d[KNN]; int id[KNN];
        merge_topk(i, d, id);
        float4 w = g_warp[i];
        float sx = 0.f, sy = 0.f, sz = 0.f;
        #pragma unroll
        for (int t = 0; t < KNN; t++) {
            float4 p = g_warp[id[t]];
            sx += p.x; sy += p.y; sz += p.z;
        }
        g_moved[i] = make_float4((sx - 10.f * w.x) / 9.f,
                                 (sy - 10.f * w.y) / 9.f,
                                 (sz - 10.f * w.z) / 9.f, 0.f);
        int k = *kptr;
        float4 f = g_flow[i];
        float sm = 0.f;
        #pragma unroll
        for (int t = 0; t < KNN; t++) {
            if (t < k) {
                float4 gfl = g_flow[id[t]];
                float dx = gfl.x - f.x, dy = gfl.y - f.y, dz = gfl.z - f.z;
                float sq = dx * dx + dy * dy + dz * dz;
                sm += sqrtf(sq);   // sq==0 (self) -> 0, matches safe-norm
            }
        }
        sm_d = (double)(sm / 8.f);
    }
    double v = warp_red(sm_d);
    if ((threadIdx.x & 31) == 0) atomicAdd(&g_acc[2], v);
}

// warp->pc2 knn -> chamfer fwd + interpolated-curvature loss
__global__ void cross_consume_kernel(int n) {
    int i = blockIdx.x * blockDim.x + threadIdx.x;
    double d1 = 0.0, cv = 0.0;
    if (i < n) {
        float d[KNN]; int id[KNN];
        merge_topk(i, d, id);
        d1 = (double)d[0];
        float w[5]; float wsum = 0.f;
        #pragma unroll
        for (int t = 0; t < 5; t++) { w[t] = 1.f / (d[t] + 1e-8f); wsum += w[t]; }
        float ix = 0.f, iy = 0.f, iz = 0.f;
        #pragma unroll
        for (int t = 0; t < 5; t++) {
            float wn = w[t] / wsum;
            float4 c = g_c2[id[t]];
            ix = fmaf(wn, c.x, ix);
            iy = fmaf(wn, c.y, iy);
            iz = fmaf(wn, c.z, iz);
        }
        float4 m = g_moved[i];
        float ex = ix - m.x, ey = iy - m.y, ez = iz - m.z;
        cv = (double)(ex * ex + ey * ey + ez * ez);
    }
    double v0 = warp_red(d1);
    double v1 = warp_red(cv);
    if ((threadIdx.x & 31) == 0) {
        atomicAdd(&g_acc[0], v0);
        atomicAdd(&g_acc[3], v1);
    }
}

// Reverse chamfer: for each pc2 point, partial min over warp chunk
__global__ void min_partial_kernel(int n) {
    __shared__ float4 sp[TPB];
    int j = blockIdx.x * TPB + threadIdx.x;
    int chunk = n / CHUNKS;
    int i0 = blockIdx.y * chunk;
    int i1 = i0 + chunk;
    float4 q = g_pc2[j < n ? j : 0];
    float qn = q.w;
    float m = 3.4e38f;
    for (int ib = i0; ib < i1; ib += TPB) {
        __syncthreads();
        sp[threadIdx.x] = g_warp[ib + threadIdx.x];
        __syncthreads();
        #pragma unroll 4
        for (int t = 0; t < TPB; t++) {
            float4 p = sp[t];
            float dot  = fmaf(q.x, p.x, fmaf(q.y, p.y, q.z * p.z));
            float dist = fmaf(-2.f, dot, qn + p.w);
            m = fminf(m, dist);
        }
    }
    if (j < n) g_pmin[j * CHUNKS + blockIdx.y] = m;
}

__global__ void rev_consume_kernel(int n) {
    int j = blockIdx.x * blockDim.x + threadIdx.x;
    double v = 0.0;
    if (j < n) {
        float m = g_pmin[j * CHUNKS];
        #pragma unroll
        for (int t = 1; t < CHUNKS; t++) m = fminf(m, g_pmin[j * CHUNKS + t]);
        v = (double)m;
    }
    double s = warp_red(v);
    if ((threadIdx.x & 31) == 0) atomicAdd(&g_acc[1], s);
}

__global__ void finalize_kernel(float* __restrict__ out) {
    if (threadIdx.x == 0) {
        double chamfer = g_acc[0] + g_acc[1];
        double total = 0.02 * chamfer      // F_CHAMFER * ALPHA0
                     + 0.006 * g_acc[3]    // F_CURVATURE * ALPHA0
                     + 0.01  * g_acc[2];   // F_SMOOTH * ALPHA0
        out[0] = (float)total;
    }
}

extern "C" void kernel_launch(void* const* d_in, const int* in_sizes, int n_in,
                              void* d_out, int out_size) {
    const float* pred   = (const float*)d_in[0];  // registration_pred (1,N,3)
    const float* gt     = (const float*)d_in[1];  // registration_gt   (1,N,3)
    const float* coords = (const float*)d_in[2];  // coords            (N,3)
    const int*   kptr   = (const int*)d_in[3];    // smoothness_k

    int n = in_sizes[2] / 3;   // 8192

    int cb = (n + 255) / 256;
    prep_kernel<<<cb, 256>>>(pred, gt, coords, n);

    dim3 gk(n / TPB, CHUNKS);
    // pc2 self-knn -> curvature
    knn_partial_kernel<1, 1><<<gk, TPB>>>(n);
    curv2_kernel<<<cb, 256>>>(n);
    // pc1 self-knn -> moved curvature + smoothness
    knn_partial_kernel<0, 0><<<gk, TPB>>>(n);
    pc1_consume_kernel<<<cb, 256>>>(n, kptr);
    // warp -> pc2 knn -> chamfer fwd + curv loss
    knn_partial_kernel<2, 1><<<gk, TPB>>>(n);
    cross_consume_kernel<<<cb, 256>>>(n);
    // reverse chamfer
    min_partial_kernel<<<gk, TPB>>>(n);
    rev_consume_kernel<<<cb, 256>>>(n);

    finalize_kernel<<<1, 32>>>((float*)d_out);
}

// round 3
// speedup vs baseline: 1.3159x; 1.3159x over previous
#include <cuda_runtime.h>
#include <cuda_bf16.h>

// PointPWC loss, B=1, N=8192.
// total = 0.02*chamfer + 0.006*curv + 0.01*smooth
//
// R2: all four O(N^2) passes fused into one launch (grid.z = 4 slices):
//   z=0: pc2 self-knn partials      z=1: pc1 self-knn partials
//   z=2: warp->pc2 knn partials     z=3: pc2->warp min (reverse chamfer)
// Then one fused consume launch (3 slices), cross-consume, finalize.

#define MAXN   8192
#define CHUNKS 8
#define KNN    10
#define TPB    128

__device__ float4 g_pc1[MAXN];
__device__ float4 g_pc2[MAXN];
__device__ float4 g_warp[MAXN];
__device__ float4 g_flow[MAXN];
__device__ float4 g_c2[MAXN];
__device__ float4 g_moved[MAXN];
// partial scratch: slice s in [0,3) -> knn partials; slice 3 -> mins
__device__ float  g_pd[3 * MAXN * CHUNKS * KNN];
__device__ int    g_pi[3 * MAXN * CHUNKS * KNN];
__device__ float  g_pmin[MAXN * CHUNKS];
__device__ double g_acc[4];  // 0: chamfer fwd, 1: chamfer bwd, 2: smooth, 3: curv

__device__ __forceinline__ double warp_red(double v) {
    #pragma unroll
    for (int o = 16; o > 0; o >>= 1)
        v += __shfl_down_sync(0xffffffffu, v, o);
    return v;
}

__global__ void prep_kernel(const float* __restrict__ pred,
                            const float* __restrict__ gt,
                            const float* __restrict__ coords, int n) {
    int i = blockIdx.x * blockDim.x + threadIdx.x;
    if (i == 0) { g_acc[0] = 0.0; g_acc[1] = 0.0; g_acc[2] = 0.0; g_acc[3] = 0.0; }
    if (i >= n) return;
    float cx = coords[3 * i + 0], cy = coords[3 * i + 1], cz = coords[3 * i + 2];
    float gx = gt[3 * i + 0],     gy = gt[3 * i + 1],     gz = gt[3 * i + 2];
    float fx = pred[3 * i + 0],   fy = pred[3 * i + 1],   fz = pred[3 * i + 2];
    float p2x = cx + gx, p2y = cy + gy, p2z = cz + gz;
    float wx  = cx + fx, wy  = cy + fy, wz  = cz + fz;
    g_pc1[i]  = make_float4(cx, cy, cz, cx * cx + cy * cy + cz * cz);
    g_pc2[i]  = make_float4(p2x, p2y, p2z, p2x * p2x + p2y * p2y + p2z * p2z);
    g_warp[i] = make_float4(wx, wy, wz, wx * wx + wy * wy + wz * wz);
    g_flow[i] = make_float4(fx, fy, fz, 0.f);
}

// One fused launch for all O(N^2) work. grid = (n/TPB, CHUNKS, 4).
// Slices 0..2: sorted partial top-KNN over candidate chunk (stable, ascending j),
// tracked as dm = |p|^2 - 2<q,p> (true dist = dm + |q|^2, constant shift per query).
// Slice 3: running min of dm (reverse chamfer).
__global__ void __launch_bounds__(TPB) pairs_kernel(int n) {
    __shared__ float4 sp[TPB];
    const int slice = blockIdx.z;

    const float4* __restrict__ Q;
    const float4* __restrict__ P;
    if      (slice == 0) { Q = g_pc2;  P = g_pc2;  }
    else if (slice == 1) { Q = g_pc1;  P = g_pc1;  }
    else if (slice == 2) { Q = g_warp; P = g_pc2;  }
    else                 { Q = g_pc2;  P = g_warp; }

    const int i = blockIdx.x * TPB + threadIdx.x;
    const int chunk = n / CHUNKS;
    const int j0 = blockIdx.y * chunk;

    float4 q = Q[i < n ? i : 0];
    const float qn = q.w;

    if (slice < 3) {
        float d[KNN]; int id[KNN];
        #pragma unroll
        for (int t = 0; t < KNN; t++) { d[t] = 3.4e38f; id[t] = 0; }
        float kth = 3.4e38f;

        for (int jb = j0; jb < j0 + chunk; jb += TPB) {
            __syncthreads();
            sp[threadIdx.x] = P[jb + threadIdx.x];
            __syncthreads();
            #pragma unroll 8
            for (int t = 0; t < TPB; t++) {
                float4 p = sp[t];
                float dot = fmaf(q.x, p.x, fmaf(q.y, p.y, q.z * p.z));
                float dm  = fmaf(-2.f, dot, p.w);
                if (dm < kth) {
                    d[KNN - 1] = dm; id[KNN - 1] = jb + t;
                    #pragma unroll
                    for (int s = KNN - 1; s > 0; --s) {
                        if (d[s] < d[s - 1]) {
                            float td = d[s]; d[s] = d[s - 1]; d[s - 1] = td;
                            int   ti = id[s]; id[s] = id[s - 1]; id[s - 1] = ti;
                        }
                    }
                    kth = d[KNN - 1];
                }
            }
        }
        if (i < n) {
            int base = ((slice * MAXN + i) * CHUNKS + blockIdx.y) * KNN;
            #pragma unroll
            for (int t = 0; t < KNN; t++) {
                g_pd[base + t] = d[t] + qn;   // restore true squared distance
                g_pi[base + t] = id[t];
            }
        }
    } else {
        float m = 3.4e38f;
        for (int jb = j0; jb < j0 + chunk; jb += TPB) {
            __syncthreads();
            sp[threadIdx.x] = P[jb + threadIdx.x];
            __syncthreads();
            #pragma unroll 8
            for (int t = 0; t < TPB; t++) {
                float4 p = sp[t];
                float dot = fmaf(q.x, p.x, fmaf(q.y, p.y, q.z * p.z));
                float dm  = fmaf(-2.f, dot, p.w);
                m = fminf(m, dm);
            }
        }
        if (i < n) g_pmin[i * CHUNKS + blockIdx.y] = m + qn;
    }
}

// Stable merge of CHUNKS sorted partials (chunk-major, ascending j within/across
// chunks) -> global top-KNN with lax.top_k tie order (earliest j wins).
__device__ __forceinline__ void merge_topk(int slice, int i, float* d, int* id) {
    #pragma unroll
    for (int t = 0; t < KNN; t++) { d[t] = 3.4e38f; id[t] = 0; }
    int base = (slice * MAXN + i) * CHUNKS * KNN;
    for (int t = 0; t < CHUNKS * KNN; t++) {
        float dist = g_pd[base + t];
        int j = g_pi[base + t];
        if (dist < d[KNN - 1]) {
            d[KNN - 1] = dist; id[KNN - 1] = j;
            #pragma unroll
            for (int s = KNN - 1; s > 0; --s) {
                if (d[s] < d[s - 1]) {
                    float td = d[s]; d[s] = d[s - 1]; d[s - 1] = td;
                    int   ti = id[s]; id[s] = id[s - 1]; id[s - 1] = ti;
                }
            }
        }
    }
}

// Fused consume: grid.y selects task.
//   y=0: pc2 self-knn -> curvature of pc2
//   y=1: pc1 self-knn -> moved curvature + smoothness accumulation
//   y=2: reverse chamfer min-reduce + accumulation
__global__ void consumeA_kernel(int n, const int* __restrict__ kptr) {
    int i = blockIdx.x * blockDim.x + threadIdx.x;
    int task = blockIdx.y;
    if (task == 0) {
        if (i >= n) return;
        float d[KNN]; int id[KNN];
        merge_topk(0, i, d, id);
        float sx = 0.f, sy = 0.f, sz = 0.f;
        #pragma unroll
        for (int t = 0; t < KNN; t++) {
            float4 p = g_pc2[id[t]];
            sx += p.x; sy += p.y; sz += p.z;
        }
        float4 c = g_pc2[i];
        g_c2[i] = make_float4((sx - 10.f * c.x) / 9.f,
                              (sy - 10.f * c.y) / 9.f,
                              (sz - 10.f * c.z) / 9.f, 0.f);
    } else if (task == 1) {
        double sm_d = 0.0;
        if (i < n) {
            float d[KNN]; int id[KNN];
            merge_topk(1, i, d, id);
            float4 w = g_warp[i];
            float sx = 0.f, sy = 0.f, sz = 0.f;
            #pragma unroll
            for (int t = 0; t < KNN; t++) {
                float4 p = g_warp[id[t]];
                sx += p.x; sy += p.y; sz += p.z;
            }
            g_moved[i] = make_float4((sx - 10.f * w.x) / 9.f,
                                     (sy - 10.f * w.y) / 9.f,
                                     (sz - 10.f * w.z) / 9.f, 0.f);
            int k = *kptr;
            float4 f = g_flow[i];
            float sm = 0.f;
            #pragma unroll
            for (int t = 0; t < KNN; t++) {
                if (t < k) {
                    float4 gfl = g_flow[id[t]];
                    float dx = gfl.x - f.x, dy = gfl.y - f.y, dz = gfl.z - f.z;
                    float sq = dx * dx + dy * dy + dz * dz;
                    sm += sqrtf(sq);   // sq==0 (self) -> 0, matches safe-norm
                }
            }
            sm_d = (double)(sm / 8.f);
        }
        double v = warp_red(sm_d);
        if ((threadIdx.x & 31) == 0) atomicAdd(&g_acc[2], v);
    } else {
        double v = 0.0;
        if (i < n) {
            float m = g_pmin[i * CHUNKS];
            #pragma unroll
            for (int t = 1; t < CHUNKS; t++) m = fminf(m, g_pmin[i * CHUNKS + t]);
            v = (double)m;
        }
        double s = warp_red(v);
        if ((threadIdx.x & 31) == 0) atomicAdd(&g_acc[1], s);
    }
}

// warp->pc2 knn -> chamfer fwd + interpolated-curvature loss
__global__ void cross_consume_kernel(int n) {
    int i = blockIdx.x * blockDim.x + threadIdx.x;
    double d1 = 0.0, cv = 0.0;
    if (i < n) {
        float d[KNN]; int id[KNN];
        merge_topk(2, i, d, id);
        d1 = (double)d[0];
        float w[5]; float wsum = 0.f;
        #pragma unroll
        for (int t = 0; t < 5; t++) { w[t] = 1.f / (d[t] + 1e-8f); wsum += w[t]; }
        float ix = 0.f, iy = 0.f, iz = 0.f;
        #pragma unroll
        for (int t = 0; t < 5; t++) {
            float wn = w[t] / wsum;
            float4 c = g_c2[id[t]];
            ix = fmaf(wn, c.x, ix);
            iy = fmaf(wn, c.y, iy);
            iz = fmaf(wn, c.z, iz);
        }
        float4 m = g_moved[i];
        float ex = ix - m.x, ey = iy - m.y, ez = iz - m.z;
        cv = (double)(ex * ex + ey * ey + ez * ez);
    }
    double v0 = warp_red(d1);
    double v1 = warp_red(cv);
    if ((threadIdx.x & 31) == 0) {
        atomicAdd(&g_acc[0], v0);
        atomicAdd(&g_acc[3], v1);
    }
}

__global__ void finalize_kernel(float* __restrict__ out) {
    if (threadIdx.x == 0) {
        double chamfer = g_acc[0] + g_acc[1];
        double total = 0.02 * chamfer      // F_CHAMFER * ALPHA0
                     + 0.006 * g_acc[3]    // F_CURVATURE * ALPHA0
                     + 0.01  * g_acc[2];   // F_SMOOTH * ALPHA0
        out[0] = (float)total;
    }
}

extern "C" void kernel_launch(void* const* d_in, const int* in_sizes, int n_in,
                              void* d_out, int out_size) {
    const float* pred   = (const float*)d_in[0];  // registration_pred (1,N,3)
    const float* gt     = (const float*)d_in[1];  // registration_gt   (1,N,3)
    const float* coords = (const float*)d_in[2];  // coords            (N,3)
    const int*   kptr   = (const int*)d_in[3];    // smoothness_k

    int n = in_sizes[2] / 3;   // 8192
    int cb = (n + 255) / 256;

    prep_kernel<<<cb, 256>>>(pred, gt, coords, n);
    pairs_kernel<<<dim3(n / TPB, CHUNKS, 4), TPB>>>(n);
    consumeA_kernel<<<dim3(cb, 3), 256>>>(n, kptr);
    cross_consume_kernel<<<cb, 256>>>(n);
    finalize_kernel<<<1, 32>>>((float*)d_out);
}